// round 14
// baseline (speedup 1.0000x reference)
#include <cuda_runtime.h>
#include <cuda_bf16.h>
#include <cstdint>

#define SEQ   2048
#define NX    768
#define NH    12
#define HD    64
#define BSZ   2
#define MROWS (BSZ*SEQ)
#define MBIAS -10000.0f

// ---------------- mma GEMM config (frag-major smem) ------------------------
#define TM 128
#define TN 128
#define TK 32
#define NSTAGE (NX / TK)       // 24

#define SM_A_HI 0
#define SM_A_LO 2048
#define SM_B_HI 4096
#define SM_B_LO 6144
#define BUFW    8192
#define GEMM_SMEM_BYTES (2 * BUFW * 4)     // 65536

// ---------------- flash config (double-buffered, split-KV, uint2 frags) ----
#define BQ 128
#define BKT 64
// per-buffer word offsets: K [n64][40], V [pr16][136], am
#define F_KHI 0
#define F_KLO 2560
#define F_VHI 5120
#define F_VLO 7296
#define F_AM  9472
#define FBUFW 9536
#define FLASH_SMEM_BYTES (2 * FBUFW * 4)   // 76288
#define NSPLIT_QT 8
#define NITEMS (NSPLIT_QT * NH * BSZ)      // 192

// LPT job table: 24 jobs per (h,b), sizes descending.
// JSP: 0/1 = kv-half of split job, -1 = whole
__device__ __constant__ signed char JQT[24] =
    {15,15,7, 14,14, 13,13,6, 12,12, 11,11,5, 10,10, 9,9,4, 8,8, 3,2,1,0};
__device__ __constant__ signed char JSP[24] =
    {0,1,-1, 0,1, 0,1,-1, 0,1, 0,1,-1, 0,1, 0,1,-1, 0,1, -1,-1,-1,-1};

// ---------------- bf16 hi/lo scratch (allocation-free: __device__) ---------
#define PAIRS_H (MROWS * NX / 2)
__device__ __align__(16) uint32_t g_hh2[PAIRS_H],  g_hl2[PAIRS_H];
__device__ __align__(16) uint32_t g_ath2[PAIRS_H], g_atl2[PAIRS_H];
__device__ __align__(16) uint32_t g_wah2[(NX/2)*3*NX], g_wal2[(NX/2)*3*NX];
__device__ __align__(16) uint32_t g_wph2[(NX/2)*NX],   g_wpl2[(NX/2)*NX];
__device__ __align__(16) uint32_t g_qh2[PAIRS_H],  g_ql2[PAIRS_H];   // 1/8 scaled
__device__ __align__(16) uint32_t g_kh2[PAIRS_H],  g_kl2[PAIRS_H];   // pair-permuted
__device__ __align__(16) uint32_t g_vh2[PAIRS_H],  g_vl2[PAIRS_H];
__device__ __align__(16) uint32_t g_vph2[PAIRS_H], g_vpl2[PAIRS_H]; // pair-row V
__device__ __align__(16) float g_oacc[(size_t)2 * NITEMS * 128 * 64];
__device__ __align__(16) float g_ml[(size_t)2 * NITEMS * 256];

#define MMA_BF16(d, a, b0, b1)                                              \
    asm volatile(                                                           \
        "mma.sync.aligned.m16n8k16.row.col.f32.bf16.bf16.f32 "              \
        "{%0,%1,%2,%3}, {%4,%5,%6,%7}, {%8,%9}, {%0,%1,%2,%3};"             \
        : "+f"((d)[0]), "+f"((d)[1]), "+f"((d)[2]), "+f"((d)[3])            \
        : "r"((a)[0]), "r"((a)[1]), "r"((a)[2]), "r"((a)[3]),               \
          "r"(b0), "r"(b1))

// hi/lo split of (x,y): hi word = {y,x} bf16x2, lo = residuals. Same bits
// as the old __float2bfloat16_rn chain, ~40% fewer instructions.
__device__ __forceinline__ void pack2(float x, float y,
                                      uint32_t& hi, uint32_t& lo) {
    uint32_t h;
    asm("cvt.rn.bf16x2.f32 %0, %1, %2;" : "=r"(h) : "f"(y), "f"(x));
    const float fx = __uint_as_float(h << 16);
    const float fy = __uint_as_float(h & 0xffff0000u);
    uint32_t l;
    asm("cvt.rn.bf16x2.f32 %0, %1, %2;" : "=r"(l) : "f"(y - fy), "f"(x - fx));
    hi = h; lo = l;
}

__device__ __forceinline__ uint32_t s2u(const void* p) {
    uint32_t a;
    asm("{ .reg .u64 t; cvta.to.shared.u64 t, %1; cvt.u32.u64 %0, t; }"
        : "=r"(a) : "l"(p));
    return a;
}
__device__ __forceinline__ void cp16(uint32_t s, const void* g) {
    asm volatile("cp.async.cg.shared.global [%0], [%1], 16;" :: "r"(s), "l"(g));
}
__device__ __forceinline__ void cpcommit() {
    asm volatile("cp.async.commit_group;" ::: "memory");
}
template<int N> __device__ __forceinline__ void cpwait() {
    asm volatile("cp.async.wait_group %0;" :: "n"(N) : "memory");
}

// ---------------------------------------------------------------------------
// Prep kernels
// ---------------------------------------------------------------------------
__global__ void prep_row_frag(const float* __restrict__ A,
                              uint32_t* __restrict__ h2, uint32_t* __restrict__ l2)
{
    const int lane = threadIdx.x & 31, wid = threadIdx.x >> 5;
    const int tile = blockIdx.x * 8 + wid;
    const int rt = tile / 48, kt = tile % 48;
    const int r  = rt * 16 + (lane >> 2);
    const int kw = kt * 8 + (lane & 3);
    const float2* Af = (const float2*)A;
    float2 v00 = Af[(size_t)r * 384 + kw];
    float2 v10 = Af[(size_t)(r + 8) * 384 + kw];
    float2 v01 = Af[(size_t)r * 384 + kw + 4];
    float2 v11 = Af[(size_t)(r + 8) * 384 + kw + 4];
    uint32_t h0,l0,h1,l1,h2w,l2w,h3,l3;
    pack2(v00.x, v00.y, h0, l0);
    pack2(v10.x, v10.y, h1, l1);
    pack2(v01.x, v01.y, h2w, l2w);
    pack2(v11.x, v11.y, h3, l3);
    const size_t idx = ((size_t)tile * 32 + lane) * 4;
    *(uint4*)(h2 + idx) = make_uint4(h0, h1, h2w, h3);
    *(uint4*)(l2 + idx) = make_uint4(l0, l1, l2w, l3);
}
__global__ void prep_colpair_frag(const float* __restrict__ B,
                                  uint32_t* __restrict__ h2, uint32_t* __restrict__ l2,
                                  int N)
{
    const int flat = blockIdx.x * 256 + threadIdx.x;
    const int j  = flat & 3;
    const int n  = (flat >> 2) % N;
    const int kt = (flat >> 2) / N;
    const int r0 = 16 * kt + 2 * j;
    uint32_t w0h, w0l, w1h, w1l;
    pack2(B[(size_t)r0 * N + n],       B[(size_t)(r0 + 1) * N + n], w0h, w0l);
    pack2(B[(size_t)(r0 + 8) * N + n], B[(size_t)(r0 + 9) * N + n], w1h, w1l);
    const size_t idx = (((size_t)kt * N + n) * 4 + j) * 2;
    *(uint2*)(h2 + idx) = make_uint2(w0h, w1h);
    *(uint2*)(l2 + idx) = make_uint2(w0l, w1l);
}
// V repack -> pair-row interleaved: [head][tile64][pr=kc*4+tg][d][half]
// half0 = seq-pair row k2=8kc+tg, half1 = k2+4 (within the 64-seq tile)
__global__ void repack_v()
{
    const int i = blockIdx.x * 256 + threadIdx.x;     // over PAIRS_H words
    const int head = i >> 16;
    const int rem  = i & 65535;
    const int tile_t = rem >> 11;
    const int rem2 = rem & 2047;
    const int pr = rem2 >> 7;
    const int d  = (rem2 >> 1) & 63;
    const int half = rem2 & 1;
    const int kc = pr >> 2, tg = pr & 3;
    const int k2 = 8 * kc + tg + 4 * half;            // local pair-row in tile
    const uint16_t* vh = (const uint16_t*)g_vh2;
    const uint16_t* vl = (const uint16_t*)g_vl2;
    const size_t s0 = (size_t)head * SEQ * HD +
                      (size_t)(tile_t * 64 + 2 * k2) * HD + d;
    g_vph2[i] = (uint32_t)vh[s0] | ((uint32_t)vh[s0 + HD] << 16);
    g_vpl2[i] = (uint32_t)vl[s0] | ((uint32_t)vl[s0 + HD] << 16);
}

// ---------------------------------------------------------------------------
// Tensor-core GEMM on frag-major operands (R13 structure; K epilogue permuted)
// ---------------------------------------------------------------------------
__global__ __launch_bounds__(256, 2)
void gemm_mma(const uint32_t* __restrict__ a2h, const uint32_t* __restrict__ a2l,
              const uint32_t* __restrict__ b2h, const uint32_t* __restrict__ b2l,
              const float* __restrict__ bias, float* __restrict__ C,
              int Ncols, int mode)
{
    extern __shared__ __align__(16) uint32_t smw[];
    const uint32_t sbase = s2u(smw);

    const int tid  = threadIdx.x;
    const int lane = tid & 31, wid = tid >> 5;
    const int warp_m = wid >> 2;
    const int warp_n = wid & 3;
    const int m0 = blockIdx.y * TM;
    const int n0 = blockIdx.x * TN;
    const int g  = lane >> 2;
    const int tg = lane & 3;
    const int rt0 = m0 >> 4;

    float acc[4][4][4];
#pragma unroll
    for (int mt = 0; mt < 4; mt++)
#pragma unroll
        for (int nt = 0; nt < 4; nt++)
#pragma unroll
            for (int j = 0; j < 4; j++) acc[mt][nt][j] = 0.f;

    auto stage = [&](int s, int buf) {
        const uint32_t so = (uint32_t)buf * BUFW;
#pragma unroll
        for (int it = 0; it < 2; it++) {
            const int c = tid + it * 256;
            const int rt = c >> 6, kt = (c >> 5) & 1, ch = c & 31;
            const size_t go = ((size_t)(rt0 + rt) * 48 + 2 * s + kt) * 128 + ch * 4;
            const uint32_t sa = sbase + (so + SM_A_HI + ((rt * 2 + kt) * 32 + ch) * 4) * 4;
            cp16(sa, a2h + go);
            cp16(sa + (SM_A_LO - SM_A_HI) * 4, a2l + go);
        }
#pragma unroll
        for (int it = 0; it < 2; it++) {
            const int c = tid + it * 256;
            const int kt = c >> 8, n = (c >> 1) & 127, half = c & 1;
            const size_t go = ((size_t)(2 * s + kt) * Ncols + n0 + n) * 8 + half * 4;
            const uint32_t sa = sbase + (so + SM_B_HI + (kt * 128 + n) * 8 + half * 4) * 4;
            cp16(sa, b2h + go);
            cp16(sa + (SM_B_LO - SM_B_HI) * 4, b2l + go);
        }
        cpcommit();
    };

    stage(0, 0);
    for (int s = 0; s < NSTAGE; s++) {
        if (s + 1 < NSTAGE) { stage(s + 1, (s + 1) & 1); cpwait<1>(); }
        else                { cpwait<0>(); }
        __syncthreads();

        const uint32_t bo = (uint32_t)(s & 1) * BUFW;
#pragma unroll
        for (int c = 0; c < 2; c++) {
            uint32_t ah[4][4], al[4][4];
#pragma unroll
            for (int mt = 0; mt < 4; mt++) {
                const uint32_t off = bo + SM_A_HI +
                    (((warp_m * 4 + mt) * 2 + c) * 32 + g * 4 + tg) * 4;
                uint4 vh = *(const uint4*)(smw + off);
                uint4 vl = *(const uint4*)(smw + off + (SM_A_LO - SM_A_HI));
                ah[mt][0] = vh.x; ah[mt][1] = vh.y; ah[mt][2] = vh.z; ah[mt][3] = vh.w;
                al[mt][0] = vl.x; al[mt][1] = vl.y; al[mt][2] = vl.z; al[mt][3] = vl.w;
            }
#pragma unroll
            for (int nt = 0; nt < 4; nt++) {
                const int ncol = warp_n * 32 + nt * 8 + g;
                const uint32_t boff = bo + SM_B_HI + (c * 128 + ncol) * 8 + tg * 2;
                uint2 vbh = *(const uint2*)(smw + boff);
                uint2 vbl = *(const uint2*)(smw + boff + (SM_B_LO - SM_B_HI));
#pragma unroll
                for (int mt = 0; mt < 4; mt++) {
                    MMA_BF16(acc[mt][nt], ah[mt], vbh.x, vbh.y);
                    MMA_BF16(acc[mt][nt], al[mt], vbh.x, vbh.y);
                    MMA_BF16(acc[mt][nt], ah[mt], vbl.x, vbl.y);
                }
            }
        }
        __syncthreads();
    }

    if (mode == 1) {
        const int which = n0 / NX;
        const int lcb = n0 - which * NX;
        uint32_t* dh = (which == 0) ? g_qh2 : (which == 1) ? g_kh2 : g_vh2;
        uint32_t* dl = (which == 0) ? g_ql2 : (which == 1) ? g_kl2 : g_vl2;
        const float sc = (which == 0) ? 0.125f : 1.0f;
#pragma unroll
        for (int mt = 0; mt < 4; mt++) {
            const int r0 = m0 + warp_m * 64 + mt * 16 + g;
#pragma unroll
            for (int nt = 0; nt < 4; nt++) {
                const int gc = n0 + warp_n * 32 + nt * 8 + tg * 2;
                const int lc = lcb + warp_n * 32 + nt * 8 + tg * 2;
                // K: permute word within head d-line so (d2, d2+4) adjacent
                int widx;
                if (which == 1) {
                    const int w = (lc & 63) >> 1;
                    const int t = w & 7;
                    widx = (lc >> 6) * 32 + ((w >> 3) << 3) + ((t & 3) << 1) + (t >> 2);
                } else {
                    widx = lc >> 1;
                }
                const float b0 = bias[gc], b1 = bias[gc + 1];
                uint32_t h, l;
                pack2((acc[mt][nt][0] + b0) * sc, (acc[mt][nt][1] + b1) * sc, h, l);
                dh[(size_t)r0 * 384 + widx] = h;
                dl[(size_t)r0 * 384 + widx] = l;
                pack2((acc[mt][nt][2] + b0) * sc, (acc[mt][nt][3] + b1) * sc, h, l);
                dh[(size_t)(r0 + 8) * 384 + widx] = h;
                dl[(size_t)(r0 + 8) * 384 + widx] = l;
            }
        }
    } else {
#pragma unroll
        for (int mt = 0; mt < 4; mt++) {
            const int r0 = m0 + warp_m * 64 + mt * 16 + g;
#pragma unroll
            for (int nt = 0; nt < 4; nt++) {
                const int gc = n0 + warp_n * 32 + nt * 8 + tg * 2;
                const float b0 = bias[gc], b1 = bias[gc + 1];
                float2 o0, o1;
                o0.x = acc[mt][nt][0] + b0; o0.y = acc[mt][nt][1] + b1;
                o1.x = acc[mt][nt][2] + b0; o1.y = acc[mt][nt][3] + b1;
                *(float2*)(C + (size_t)r0 * Ncols + gc)       = o0;
                *(float2*)(C + (size_t)(r0 + 8) * Ncols + gc) = o1;
            }
        }
    }
}

// ---------------------------------------------------------------------------
// Flash attention: LPT 24-job map, uint2 K/V fragment loads.
// ---------------------------------------------------------------------------
__global__ __launch_bounds__(256, 2)
void flash_mma(const float* __restrict__ am_g)
{
    extern __shared__ __align__(16) uint32_t smw[];
    const uint32_t sbase = s2u(smw);

    const int tid = threadIdx.x;
    const int lane = tid & 31, wid = tid >> 5;
    const int g = lane >> 2, tg = lane & 3;
    const int idx = blockIdx.x;
    const int h = blockIdx.y, b = blockIdx.z;

    const int qt = JQT[idx];
    const int jsp = JSP[idx];
    const bool split = (jsp >= 0);
    const int sp = split ? jsp : 0;
    const int klo = (split && sp) ? (qt + 1) : 0;
    const int khi = split ? (sp ? (2 * qt + 2) : (qt + 1)) : (2 * qt + 2);

    const size_t hoffw = (size_t)b * (SEQ * NX / 2) + (size_t)h * (SEQ * HD / 2);
    const uint32_t* Qh2 = g_qh2 + hoffw;
    const uint32_t* Ql2 = g_ql2 + hoffw;
    const uint32_t* Kh2 = g_kh2 + hoffw;
    const uint32_t* Kl2 = g_kl2 + hoffw;
    const uint32_t* Vph = g_vph2 + hoffw;
    const uint32_t* Vpl = g_vpl2 + hoffw;
    const float* am = am_g + (size_t)b * SEQ;
    const int q0 = qt * BQ;
    const int qg0 = q0 + wid * 16 + g;
    const int qg1 = qg0 + 8;

    uint32_t qfh[4][4], qfl[4][4];
#pragma unroll
    for (int kc = 0; kc < 4; kc++) {
        const size_t i0 = (size_t)qg0 * 32 + 8 * kc + tg;
        const size_t i1 = (size_t)qg1 * 32 + 8 * kc + tg;
        qfh[kc][0] = Qh2[i0];     qfl[kc][0] = Ql2[i0];
        qfh[kc][1] = Qh2[i1];     qfl[kc][1] = Ql2[i1];
        qfh[kc][2] = Qh2[i0 + 4]; qfl[kc][2] = Ql2[i0 + 4];
        qfh[kc][3] = Qh2[i1 + 4]; qfl[kc][3] = Ql2[i1 + 4];
    }

    float mx0 = -1e30f, mx1 = -1e30f, ls0 = 0.f, ls1 = 0.f;
    float accO[8][4];
#pragma unroll
    for (int nt = 0; nt < 8; nt++)
#pragma unroll
        for (int j = 0; j < 4; j++) accO[nt][j] = 0.f;

    auto stageF = [&](int kt, int buf) {
        const int k0 = kt * BKT;
        const uint32_t so = sbase + (uint32_t)buf * (FBUFW * 4);
        // K: [n][40], 32 contiguous words per n (pair-permuted content)
#pragma unroll
        for (int it = 0; it < 2; it++) {
            const int c = tid + it * 256;
            const int n = c >> 3, q4 = (c & 7) * 4;
            const size_t go = (size_t)(k0 + n) * 32 + q4;
            cp16(so + (F_KHI + n * 40 + q4) * 4, Kh2 + go);
            cp16(so + (F_KLO + n * 40 + q4) * 4, Kl2 + go);
        }
        // V: [pr][136], tile is 2048 contiguous words
#pragma unroll
        for (int it = 0; it < 2; it++) {
            const int c = tid + it * 256;
            const int pr = c >> 5, w4 = (c & 31) * 4;
            const size_t go = (size_t)kt * 2048 + pr * 128 + w4;
            cp16(so + (F_VHI + pr * 136 + w4) * 4, Vph + go);
            cp16(so + (F_VLO + pr * 136 + w4) * 4, Vpl + go);
        }
        if (tid < 16) cp16(so + (F_AM + tid * 4) * 4, am + k0 + tid * 4);
        cpcommit();
    };

    stageF(klo, 0);
    for (int kt = klo; kt < khi; kt++) {
        cpwait<0>();
        __syncthreads();
        if (kt + 1 < khi) stageF(kt + 1, (kt + 1 - klo) & 1);

        const uint32_t* bp = smw + (uint32_t)((kt - klo) & 1) * FBUFW;
        const float* amf = (const float*)(bp + F_AM);
        const int k0 = kt * BKT;

        float s[8][4];
#pragma unroll
        for (int nt = 0; nt < 8; nt++)
#pragma unroll
            for (int j = 0; j < 4; j++) s[nt][j] = 0.f;

#pragma unroll
        for (int kc = 0; kc < 4; kc++) {
#pragma unroll
            for (int nt = 0; nt < 8; nt++) {
                const uint32_t koff = (8 * nt + g) * 40 + 8 * kc + 2 * tg;
                uint2 kh = *(const uint2*)(bp + F_KHI + koff);
                uint2 kl = *(const uint2*)(bp + F_KLO + koff);
                MMA_BF16(s[nt], qfh[kc], kh.x, kh.y);
                MMA_BF16(s[nt], qfl[kc], kh.x, kh.y);
                MMA_BF16(s[nt], qfh[kc], kl.x, kl.y);
            }
        }

        const bool need_mask = (kt >= 2 * qt);
#pragma unroll
        for (int nt = 0; nt < 8; nt++) {
            const int kg = k0 + 8 * nt + 2 * tg;
            const float a0 = amf[8 * nt + 2 * tg];
            const float a1 = amf[8 * nt + 2 * tg + 1];
            if (need_mask) {
                s[nt][0] = (kg     <= qg0) ? s[nt][0] + a0 : MBIAS + a0;
                s[nt][1] = (kg + 1 <= qg0) ? s[nt][1] + a1 : MBIAS + a1;
                s[nt][2] = (kg     <= qg1) ? s[nt][2] + a0 : MBIAS + a0;
                s[nt][3] = (kg + 1 <= qg1) ? s[nt][3] + a1 : MBIAS + a1;
            } else {
                s[nt][0] += a0; s[nt][1] += a1;
                s[nt][2] += a0; s[nt][3] += a1;
            }
        }

        float t0 = -1e30f, t1 = -1e30f;
#pragma unroll
        for (int nt = 0; nt < 8; nt++) {
            t0 = fmaxf(t0, fmaxf(s[nt][0], s[nt][1]));
            t1 = fmaxf(t1, fmaxf(s[nt][2], s[nt][3]));
        }
#pragma unroll
        for (int off = 1; off <= 2; off <<= 1) {
            t0 = fmaxf(t0, __shfl_xor_sync(0xffffffffu, t0, off));
            t1 = fmaxf(t1, __shfl_xor_sync(0xffffffffu, t1, off));
        }
        const float mn0 = fmaxf(mx0, t0), mn1 = fmaxf(mx1, t1);
        const float corr0 = __expf(mx0 - mn0), corr1 = __expf(mx1 - mn1);
        mx0 = mn0; mx1 = mn1;

        float sum0 = 0.f, sum1 = 0.f;
#pragma unroll
        for (int nt = 0; nt < 8; nt++) {
            s[nt][0] = __expf(s[nt][0] - mn0);
            s[nt][1] = __expf(s[nt][1] - mn0);
            s[nt][2] = __expf(s[nt][2] - mn1);
            s[nt][3] = __expf(s[nt][3] - mn1);
            sum0 += s[nt][0] + s[nt][1];
            sum1 += s[nt][2] + s[nt][3];
        }
#pragma unroll
        for (int off = 1; off <= 2; off <<= 1) {
            sum0 += __shfl_xor_sync(0xffffffffu, sum0, off);
            sum1 += __shfl_xor_sync(0xffffffffu, sum1, off);
        }
        ls0 = ls0 * corr0 + sum0;
        ls1 = ls1 * corr1 + sum1;
#pragma unroll
        for (int nt = 0; nt < 8; nt++) {
            accO[nt][0] *= corr0; accO[nt][1] *= corr0;
            accO[nt][2] *= corr1; accO[nt][3] *= corr1;
        }

        uint32_t ph[4][4], pl[4][4];
#pragma unroll
        for (int kc = 0; kc < 4; kc++) {
            pack2(s[2 * kc][0],     s[2 * kc][1],     ph[kc][0], pl[kc][0]);
            pack2(s[2 * kc][2],     s[2 * kc][3],     ph[kc][1], pl[kc][1]);
            pack2(s[2 * kc + 1][0], s[2 * kc + 1][1], ph[kc][2], pl[kc][2]);
            pack2(s[2 * kc + 1][2], s[2 * kc + 1][3], ph[kc][3], pl[kc][3]);
        }

#pragma unroll
        for (int kc = 0; kc < 4; kc++) {
#pragma unroll
            for (int nt = 0; nt < 8; nt++) {
                const uint32_t voff = (kc * 4 + tg) * 136 + (8 * nt + g) * 2;
                uint2 vh = *(const uint2*)(bp + F_VHI + voff);
                uint2 vl = *(const uint2*)(bp + F_VLO + voff);
                MMA_BF16(accO[nt], ph[kc], vh.x, vh.y);
                MMA_BF16(accO[nt], pl[kc], vh.x, vh.y);
                MMA_BF16(accO[nt], ph[kc], vl.x, vl.y);
            }
        }
    }

    if (!split) {
        const float inv0 = 1.0f / ls0, inv1 = 1.0f / ls1;
        const int rt = b * 128 + qt * 8 + wid;
#pragma unroll
        for (int np = 0; np < 4; np++) {
            const int nt0 = 2 * np, nt1 = nt0 + 1;
            uint32_t w0h,w0l,w1h,w1l,w2h,w2l,w3h,w3l;
            pack2(accO[nt0][0] * inv0, accO[nt0][1] * inv0, w0h, w0l);
            pack2(accO[nt0][2] * inv1, accO[nt0][3] * inv1, w1h, w1l);
            pack2(accO[nt1][0] * inv0, accO[nt1][1] * inv0, w2h, w2l);
            pack2(accO[nt1][2] * inv1, accO[nt1][3] * inv1, w3h, w3l);
            const size_t fi = (((size_t)rt * 48 + h * 4 + np) * 32 + g * 4 + tg) * 4;
            *(uint4*)(g_ath2 + fi) = make_uint4(w0h, w1h, w2h, w3h);
            *(uint4*)(g_atl2 + fi) = make_uint4(w0l, w1l, w2l, w3l);
        }
    } else {
        const int item = (b * NH + h) * NSPLIT_QT + (qt - 8);
        const int sidx = item * 2 + sp;
        float* Op = g_oacc + (size_t)sidx * 128 * 64;
        const int r0 = qg0 - q0, r1 = r0 + 8;
#pragma unroll
        for (int nt = 0; nt < 8; nt++) {
            const int col = 8 * nt + 2 * tg;
            *(float2*)(Op + r0 * 64 + col) = make_float2(accO[nt][0], accO[nt][1]);
            *(float2*)(Op + r1 * 64 + col) = make_float2(accO[nt][2], accO[nt][3]);
        }
        if (tg == 0) {
            g_ml[(size_t)sidx * 256 + r0]       = mx0;
            g_ml[(size_t)sidx * 256 + 128 + r0] = ls0;
            g_ml[(size_t)sidx * 256 + r1]       = mx1;
            g_ml[(size_t)sidx * 256 + 128 + r1] = ls1;
        }
    }
}

// ---------------------------------------------------------------------------
// Merge the two kv-splits; writes frag-major A words.
// ---------------------------------------------------------------------------
__global__ __launch_bounds__(256)
void merge_split()
{
    const int item = blockIdx.y;
    const int qt = item % NSPLIT_QT + 8;
    const int hb = item / NSPLIT_QT;
    const int h = hb % NH, b = hb / NH;
    const int flat = blockIdx.x * 256 + threadIdx.x;
    const int r = flat >> 5, dp = flat & 31;

    const int s0 = item * 2, s1 = s0 + 1;
    const float m0 = g_ml[(size_t)s0 * 256 + r];
    const float l0 = g_ml[(size_t)s0 * 256 + 128 + r];
    const float m1 = g_ml[(size_t)s1 * 256 + r];
    const float l1 = g_ml[(size_t)s1 * 256 + 128 + r];
    const float m  = fmaxf(m0, m1);
    const float c0 = __expf(m0 - m), c1 = __expf(m1 - m);
    const float inv = 1.0f / (c0 * l0 + c1 * l1);

    const float2 o0 = *(const float2*)(g_oacc + ((size_t)s0 * 128 + r) * 64 + 2 * dp);
    const float2 o1 = *(const float2*)(g_oacc + ((size_t)s1 * 128 + r) * 64 + 2 * dp);
    const float v0 = (c0 * o0.x + c1 * o1.x) * inv;
    const float v1 = (c0 * o0.y + c1 * o1.y) * inv;
    uint32_t hh, ll;
    pack2(v0, v1, hh, ll);
    const int rowg = b * SEQ + qt * BQ + r;
    const int kw = h * 32 + dp;
    const size_t fi = (((size_t)(rowg >> 4) * 48 + (kw >> 3)) * 32 +
                       (rowg & 7) * 4 + (kw & 3)) * 4 +
                      ((rowg >> 3) & 1) + 2 * ((kw >> 2) & 1);
    g_ath2[fi] = hh;
    g_atl2[fi] = ll;
}

// ---------------------------------------------------------------------------
extern "C" void kernel_launch(void* const* d_in, const int* in_sizes, int n_in,
                              void* d_out, int out_size)
{
    const float* hidden = (const float*)d_in[0];
    const float* amask  = (const float*)d_in[1];
    const float* w_attn = (const float*)d_in[2];
    const float* b_attn = (const float*)d_in[3];
    const float* w_proj = (const float*)d_in[4];
    const float* b_proj = (const float*)d_in[5];
    float* out = (float*)d_out;

    cudaFuncSetAttribute(gemm_mma,
        cudaFuncAttributeMaxDynamicSharedMemorySize, GEMM_SMEM_BYTES);
    cudaFuncSetAttribute(flash_mma,
        cudaFuncAttributeMaxDynamicSharedMemorySize, FLASH_SMEM_BYTES);

    uint32_t *hh2, *hl2, *wah2, *wal2, *wph2, *wpl2, *ath2, *atl2;
    cudaGetSymbolAddress((void**)&hh2,  g_hh2);
    cudaGetSymbolAddress((void**)&hl2,  g_hl2);
    cudaGetSymbolAddress((void**)&wah2, g_wah2);
    cudaGetSymbolAddress((void**)&wal2, g_wal2);
    cudaGetSymbolAddress((void**)&wph2, g_wph2);
    cudaGetSymbolAddress((void**)&wpl2, g_wpl2);
    cudaGetSymbolAddress((void**)&ath2, g_ath2);
    cudaGetSymbolAddress((void**)&atl2, g_atl2);

    // 0) precompute operands: A frag-major, B frag-pair
    prep_row_frag<<<(MROWS / 16) * 48 / 8, 256>>>(hidden, hh2, hl2);
    prep_colpair_frag<<<48 * (3 * NX) * 4 / 256, 256>>>(w_attn, wah2, wal2, 3 * NX);
    prep_colpair_frag<<<48 * NX * 4 / 256, 256>>>(w_proj, wph2, wpl2, NX);

    // 1) QKV projection -> q (scaled) / k (pair-permuted) / v bf16 hi/lo
    gemm_mma<<<dim3(3 * NX / TN, MROWS / TM), 256, GEMM_SMEM_BYTES>>>(
        hh2, hl2, wah2, wal2, b_attn, nullptr, 3 * NX, 1);

    // 1b) V pair-row repack for uint2 flash fragments
    repack_v<<<PAIRS_H / 256, 256>>>();

    // 2) Causal flash attention, LPT split-KV (24 jobs per (h,b))
    flash_mma<<<dim3(24, NH, BSZ), 256, FLASH_SMEM_BYTES>>>(amask);

    // 2b) merge kv-splits
    merge_split<<<dim3(16, NITEMS), 256>>>();

    // 3) Output projection -> fp32 out
    gemm_mma<<<dim3(NX / TN, MROWS / TM), 256, GEMM_SMEM_BYTES>>>(
        ath2, atl2, wph2, wpl2, b_proj, out, NX, 2);
}

// round 15
// speedup vs baseline: 1.5403x; 1.5403x over previous
#include <cuda_runtime.h>
#include <cuda_bf16.h>
#include <cstdint>

#define SEQ   2048
#define NX    768
#define NH    12
#define HD    64
#define BSZ   2
#define MROWS (BSZ*SEQ)
#define MBIAS -10000.0f

// ---------------- mma GEMM config (frag-major smem) ------------------------
#define TM 128
#define TN 128
#define TK 32
#define NSTAGE (NX / TK)       // 24

#define SM_A_HI 0
#define SM_A_LO 2048
#define SM_B_HI 4096
#define SM_B_LO 6144
#define BUFW    8192
#define GEMM_SMEM_BYTES (2 * BUFW * 4)     // 65536

// ---------------- flash config (double-buffered, split-KV, uint2 frags) ----
#define BQ 128
#define BKT 64
// per-buffer word offsets: K [n64][40], V [pr16][136], am
#define F_KHI 0
#define F_KLO 2560
#define F_VHI 5120
#define F_VLO 7296
#define F_AM  9472
#define FBUFW 9536
#define FLASH_SMEM_BYTES (2 * FBUFW * 4)   // 76288
#define NSPLIT_QT 8
#define NITEMS (NSPLIT_QT * NH * BSZ)      // 192

// LPT job table: 24 jobs per (h,b), sizes descending.
// JSP: 0/1 = kv-half of split job, -1 = whole
__device__ __constant__ signed char JQT[24] =
    {15,15,7, 14,14, 13,13,6, 12,12, 11,11,5, 10,10, 9,9,4, 8,8, 3,2,1,0};
__device__ __constant__ signed char JSP[24] =
    {0,1,-1, 0,1, 0,1,-1, 0,1, 0,1,-1, 0,1, 0,1,-1, 0,1, -1,-1,-1,-1};

// ---------------- bf16 hi/lo scratch (allocation-free: __device__) ---------
#define PAIRS_H (MROWS * NX / 2)
__device__ __align__(16) uint32_t g_hh2[PAIRS_H],  g_hl2[PAIRS_H];
__device__ __align__(16) uint32_t g_ath2[PAIRS_H], g_atl2[PAIRS_H];
__device__ __align__(16) uint32_t g_wah2[(NX/2)*3*NX], g_wal2[(NX/2)*3*NX];
__device__ __align__(16) uint32_t g_wph2[(NX/2)*NX],   g_wpl2[(NX/2)*NX];
__device__ __align__(16) uint32_t g_qh2[PAIRS_H],  g_ql2[PAIRS_H];   // 1/8 scaled
__device__ __align__(16) uint32_t g_kh2[PAIRS_H],  g_kl2[PAIRS_H];   // pair-permuted
__device__ __align__(16) uint32_t g_vh2[PAIRS_H],  g_vl2[PAIRS_H];
__device__ __align__(16) uint32_t g_vph2[PAIRS_H], g_vpl2[PAIRS_H]; // pair-row V
__device__ __align__(16) float g_oacc[(size_t)2 * NITEMS * 128 * 64];
__device__ __align__(16) float g_ml[(size_t)2 * NITEMS * 256];

#define MMA_BF16(d, a, b0, b1)                                              \
    asm volatile(                                                           \
        "mma.sync.aligned.m16n8k16.row.col.f32.bf16.bf16.f32 "              \
        "{%0,%1,%2,%3}, {%4,%5,%6,%7}, {%8,%9}, {%0,%1,%2,%3};"             \
        : "+f"((d)[0]), "+f"((d)[1]), "+f"((d)[2]), "+f"((d)[3])            \
        : "r"((a)[0]), "r"((a)[1]), "r"((a)[2]), "r"((a)[3]),               \
          "r"(b0), "r"(b1))

// hi/lo split of (x,y): hi word = {y,x} bf16x2, lo = residuals.
__device__ __forceinline__ void pack2(float x, float y,
                                      uint32_t& hi, uint32_t& lo) {
    uint32_t h;
    asm("cvt.rn.bf16x2.f32 %0, %1, %2;" : "=r"(h) : "f"(y), "f"(x));
    const float fx = __uint_as_float(h << 16);
    const float fy = __uint_as_float(h & 0xffff0000u);
    uint32_t l;
    asm("cvt.rn.bf16x2.f32 %0, %1, %2;" : "=r"(l) : "f"(y - fy), "f"(x - fx));
    hi = h; lo = l;
}

__device__ __forceinline__ uint32_t s2u(const void* p) {
    uint32_t a;
    asm("{ .reg .u64 t; cvta.to.shared.u64 t, %1; cvt.u32.u64 %0, t; }"
        : "=r"(a) : "l"(p));
    return a;
}
__device__ __forceinline__ void cp16(uint32_t s, const void* g) {
    asm volatile("cp.async.cg.shared.global [%0], [%1], 16;" :: "r"(s), "l"(g));
}
__device__ __forceinline__ void cpcommit() {
    asm volatile("cp.async.commit_group;" ::: "memory");
}
template<int N> __device__ __forceinline__ void cpwait() {
    asm volatile("cp.async.wait_group %0;" :: "n"(N) : "memory");
}

// ---------------------------------------------------------------------------
// Prep kernels
// ---------------------------------------------------------------------------
__global__ void prep_row_frag(const float* __restrict__ A,
                              uint32_t* __restrict__ h2, uint32_t* __restrict__ l2)
{
    const int lane = threadIdx.x & 31, wid = threadIdx.x >> 5;
    const int tile = blockIdx.x * 8 + wid;
    const int rt = tile / 48, kt = tile % 48;
    const int r  = rt * 16 + (lane >> 2);
    const int kw = kt * 8 + (lane & 3);
    const float2* Af = (const float2*)A;
    float2 v00 = Af[(size_t)r * 384 + kw];
    float2 v10 = Af[(size_t)(r + 8) * 384 + kw];
    float2 v01 = Af[(size_t)r * 384 + kw + 4];
    float2 v11 = Af[(size_t)(r + 8) * 384 + kw + 4];
    uint32_t h0,l0,h1,l1,h2w,l2w,h3,l3;
    pack2(v00.x, v00.y, h0, l0);
    pack2(v10.x, v10.y, h1, l1);
    pack2(v01.x, v01.y, h2w, l2w);
    pack2(v11.x, v11.y, h3, l3);
    const size_t idx = ((size_t)tile * 32 + lane) * 4;
    *(uint4*)(h2 + idx) = make_uint4(h0, h1, h2w, h3);
    *(uint4*)(l2 + idx) = make_uint4(l0, l1, l2w, l3);
}
__global__ void prep_colpair_frag(const float* __restrict__ B,
                                  uint32_t* __restrict__ h2, uint32_t* __restrict__ l2,
                                  int N)
{
    const int flat = blockIdx.x * 256 + threadIdx.x;
    const int j  = flat & 3;
    const int n  = (flat >> 2) % N;
    const int kt = (flat >> 2) / N;
    const int r0 = 16 * kt + 2 * j;
    uint32_t w0h, w0l, w1h, w1l;
    pack2(B[(size_t)r0 * N + n],       B[(size_t)(r0 + 1) * N + n], w0h, w0l);
    pack2(B[(size_t)(r0 + 8) * N + n], B[(size_t)(r0 + 9) * N + n], w1h, w1l);
    const size_t idx = (((size_t)kt * N + n) * 4 + j) * 2;
    *(uint2*)(h2 + idx) = make_uint2(w0h, w1h);
    *(uint2*)(l2 + idx) = make_uint2(w0l, w1l);
}
// V repack -> pair-row interleaved: [head][tile64][pr=kc*4+tg][d][half]
__global__ void repack_v()
{
    const int i = blockIdx.x * 256 + threadIdx.x;
    const int head = i >> 16;
    const int rem  = i & 65535;
    const int tile_t = rem >> 11;
    const int rem2 = rem & 2047;
    const int pr = rem2 >> 7;
    const int d  = (rem2 >> 1) & 63;
    const int half = rem2 & 1;
    const int kc = pr >> 2, tg = pr & 3;
    const int k2 = 8 * kc + tg + 4 * half;
    const uint16_t* vh = (const uint16_t*)g_vh2;
    const uint16_t* vl = (const uint16_t*)g_vl2;
    const size_t s0 = (size_t)head * SEQ * HD +
                      (size_t)(tile_t * 64 + 2 * k2) * HD + d;
    g_vph2[i] = (uint32_t)vh[s0] | ((uint32_t)vh[s0 + HD] << 16);
    g_vpl2[i] = (uint32_t)vl[s0] | ((uint32_t)vl[s0 + HD] << 16);
}

// ---------------------------------------------------------------------------
// Tensor-core GEMM on frag-major operands (R13 structure; K epilogue permuted)
// ---------------------------------------------------------------------------
__global__ __launch_bounds__(256, 2)
void gemm_mma(const uint32_t* __restrict__ a2h, const uint32_t* __restrict__ a2l,
              const uint32_t* __restrict__ b2h, const uint32_t* __restrict__ b2l,
              const float* __restrict__ bias, float* __restrict__ C,
              int Ncols, int mode)
{
    extern __shared__ __align__(16) uint32_t smw[];
    const uint32_t sbase = s2u(smw);

    const int tid  = threadIdx.x;
    const int lane = tid & 31, wid = tid >> 5;
    const int warp_m = wid >> 2;
    const int warp_n = wid & 3;
    const int m0 = blockIdx.y * TM;
    const int n0 = blockIdx.x * TN;
    const int g  = lane >> 2;
    const int tg = lane & 3;
    const int rt0 = m0 >> 4;

    float acc[4][4][4];
#pragma unroll
    for (int mt = 0; mt < 4; mt++)
#pragma unroll
        for (int nt = 0; nt < 4; nt++)
#pragma unroll
            for (int j = 0; j < 4; j++) acc[mt][nt][j] = 0.f;

    auto stage = [&](int s, int buf) {
        const uint32_t so = (uint32_t)buf * BUFW;
#pragma unroll
        for (int it = 0; it < 2; it++) {
            const int c = tid + it * 256;
            const int rt = c >> 6, kt = (c >> 5) & 1, ch = c & 31;
            const size_t go = ((size_t)(rt0 + rt) * 48 + 2 * s + kt) * 128 + ch * 4;
            const uint32_t sa = sbase + (so + SM_A_HI + ((rt * 2 + kt) * 32 + ch) * 4) * 4;
            cp16(sa, a2h + go);
            cp16(sa + (SM_A_LO - SM_A_HI) * 4, a2l + go);
        }
#pragma unroll
        for (int it = 0; it < 2; it++) {
            const int c = tid + it * 256;
            const int kt = c >> 8, n = (c >> 1) & 127, half = c & 1;
            const size_t go = ((size_t)(2 * s + kt) * Ncols + n0 + n) * 8 + half * 4;
            const uint32_t sa = sbase + (so + SM_B_HI + (kt * 128 + n) * 8 + half * 4) * 4;
            cp16(sa, b2h + go);
            cp16(sa + (SM_B_LO - SM_B_HI) * 4, b2l + go);
        }
        cpcommit();
    };

    stage(0, 0);
    for (int s = 0; s < NSTAGE; s++) {
        if (s + 1 < NSTAGE) { stage(s + 1, (s + 1) & 1); cpwait<1>(); }
        else                { cpwait<0>(); }
        __syncthreads();

        const uint32_t bo = (uint32_t)(s & 1) * BUFW;
#pragma unroll
        for (int c = 0; c < 2; c++) {
            uint32_t ah[4][4], al[4][4];
#pragma unroll
            for (int mt = 0; mt < 4; mt++) {
                const uint32_t off = bo + SM_A_HI +
                    (((warp_m * 4 + mt) * 2 + c) * 32 + g * 4 + tg) * 4;
                uint4 vh = *(const uint4*)(smw + off);
                uint4 vl = *(const uint4*)(smw + off + (SM_A_LO - SM_A_HI));
                ah[mt][0] = vh.x; ah[mt][1] = vh.y; ah[mt][2] = vh.z; ah[mt][3] = vh.w;
                al[mt][0] = vl.x; al[mt][1] = vl.y; al[mt][2] = vl.z; al[mt][3] = vl.w;
            }
#pragma unroll
            for (int nt = 0; nt < 4; nt++) {
                const int ncol = warp_n * 32 + nt * 8 + g;
                const uint32_t boff = bo + SM_B_HI + (c * 128 + ncol) * 8 + tg * 2;
                uint2 vbh = *(const uint2*)(smw + boff);
                uint2 vbl = *(const uint2*)(smw + boff + (SM_B_LO - SM_B_HI));
#pragma unroll
                for (int mt = 0; mt < 4; mt++) {
                    MMA_BF16(acc[mt][nt], ah[mt], vbh.x, vbh.y);
                    MMA_BF16(acc[mt][nt], al[mt], vbh.x, vbh.y);
                    MMA_BF16(acc[mt][nt], ah[mt], vbl.x, vbl.y);
                }
            }
        }
        __syncthreads();
    }

    if (mode == 1) {
        const int which = n0 / NX;
        const int lcb = n0 - which * NX;
        uint32_t* dh = (which == 0) ? g_qh2 : (which == 1) ? g_kh2 : g_vh2;
        uint32_t* dl = (which == 0) ? g_ql2 : (which == 1) ? g_kl2 : g_vl2;
        const float sc = (which == 0) ? 0.125f : 1.0f;
#pragma unroll
        for (int mt = 0; mt < 4; mt++) {
            const int r0 = m0 + warp_m * 64 + mt * 16 + g;
#pragma unroll
            for (int nt = 0; nt < 4; nt++) {
                const int gc = n0 + warp_n * 32 + nt * 8 + tg * 2;
                const int lc = lcb + warp_n * 32 + nt * 8 + tg * 2;
                int widx;
                if (which == 1) {
                    const int w = (lc & 63) >> 1;
                    const int t = w & 7;
                    widx = (lc >> 6) * 32 + ((w >> 3) << 3) + ((t & 3) << 1) + (t >> 2);
                } else {
                    widx = lc >> 1;
                }
                const float b0 = bias[gc], b1 = bias[gc + 1];
                uint32_t h, l;
                pack2((acc[mt][nt][0] + b0) * sc, (acc[mt][nt][1] + b1) * sc, h, l);
                dh[(size_t)r0 * 384 + widx] = h;
                dl[(size_t)r0 * 384 + widx] = l;
                pack2((acc[mt][nt][2] + b0) * sc, (acc[mt][nt][3] + b1) * sc, h, l);
                dh[(size_t)(r0 + 8) * 384 + widx] = h;
                dl[(size_t)(r0 + 8) * 384 + widx] = l;
            }
        }
    } else {
#pragma unroll
        for (int mt = 0; mt < 4; mt++) {
            const int r0 = m0 + warp_m * 64 + mt * 16 + g;
#pragma unroll
            for (int nt = 0; nt < 4; nt++) {
                const int gc = n0 + warp_n * 32 + nt * 8 + tg * 2;
                const float b0 = bias[gc], b1 = bias[gc + 1];
                float2 o0, o1;
                o0.x = acc[mt][nt][0] + b0; o0.y = acc[mt][nt][1] + b1;
                o1.x = acc[mt][nt][2] + b0; o1.y = acc[mt][nt][3] + b1;
                *(float2*)(C + (size_t)r0 * Ncols + gc)       = o0;
                *(float2*)(C + (size_t)(r0 + 8) * Ncols + gc) = o1;
            }
        }
    }
}

// ---------------------------------------------------------------------------
// Flash attention: LPT 24-job map, uint2 K/V fragment loads.
// ---------------------------------------------------------------------------
__global__ __launch_bounds__(256, 2)
void flash_mma(const float* __restrict__ am_g)
{
    extern __shared__ __align__(16) uint32_t smw[];
    const uint32_t sbase = s2u(smw);

    const int tid = threadIdx.x;
    const int lane = tid & 31, wid = tid >> 5;
    const int g = lane >> 2, tg = lane & 3;
    const int idx = blockIdx.x;
    const int h = blockIdx.y, b = blockIdx.z;

    const int qt = JQT[idx];
    const int jsp = JSP[idx];
    const bool split = (jsp >= 0);
    const int sp = split ? jsp : 0;
    const int klo = (split && sp) ? (qt + 1) : 0;
    const int khi = split ? (sp ? (2 * qt + 2) : (qt + 1)) : (2 * qt + 2);

    const size_t hoffw = (size_t)b * (SEQ * NX / 2) + (size_t)h * (SEQ * HD / 2);
    const uint32_t* Qh2 = g_qh2 + hoffw;
    const uint32_t* Ql2 = g_ql2 + hoffw;
    const uint32_t* Kh2 = g_kh2 + hoffw;
    const uint32_t* Kl2 = g_kl2 + hoffw;
    const uint32_t* Vph = g_vph2 + hoffw;
    const uint32_t* Vpl = g_vpl2 + hoffw;
    const float* am = am_g + (size_t)b * SEQ;
    const int q0 = qt * BQ;
    const int qg0 = q0 + wid * 16 + g;
    const int qg1 = qg0 + 8;

    uint32_t qfh[4][4], qfl[4][4];
#pragma unroll
    for (int kc = 0; kc < 4; kc++) {
        const size_t i0 = (size_t)qg0 * 32 + 8 * kc + tg;
        const size_t i1 = (size_t)qg1 * 32 + 8 * kc + tg;
        qfh[kc][0] = Qh2[i0];     qfl[kc][0] = Ql2[i0];
        qfh[kc][1] = Qh2[i1];     qfl[kc][1] = Ql2[i1];
        qfh[kc][2] = Qh2[i0 + 4]; qfl[kc][2] = Ql2[i0 + 4];
        qfh[kc][3] = Qh2[i1 + 4]; qfl[kc][3] = Ql2[i1 + 4];
    }

    float mx0 = -1e30f, mx1 = -1e30f, ls0 = 0.f, ls1 = 0.f;
    float accO[8][4];
#pragma unroll
    for (int nt = 0; nt < 8; nt++)
#pragma unroll
        for (int j = 0; j < 4; j++) accO[nt][j] = 0.f;

    auto stageF = [&](int kt, int buf) {
        const int k0 = kt * BKT;
        const uint32_t so = sbase + (uint32_t)buf * (FBUFW * 4);
#pragma unroll
        for (int it = 0; it < 2; it++) {
            const int c = tid + it * 256;
            const int n = c >> 3, q4 = (c & 7) * 4;
            const size_t go = (size_t)(k0 + n) * 32 + q4;
            cp16(so + (F_KHI + n * 40 + q4) * 4, Kh2 + go);
            cp16(so + (F_KLO + n * 40 + q4) * 4, Kl2 + go);
        }
#pragma unroll
        for (int it = 0; it < 2; it++) {
            const int c = tid + it * 256;
            const int pr = c >> 5, w4 = (c & 31) * 4;
            const size_t go = (size_t)kt * 2048 + pr * 128 + w4;
            cp16(so + (F_VHI + pr * 136 + w4) * 4, Vph + go);
            cp16(so + (F_VLO + pr * 136 + w4) * 4, Vpl + go);
        }
        if (tid < 16) cp16(so + (F_AM + tid * 4) * 4, am + k0 + tid * 4);
        cpcommit();
    };

    stageF(klo, 0);
    for (int kt = klo; kt < khi; kt++) {
        cpwait<0>();
        __syncthreads();
        if (kt + 1 < khi) stageF(kt + 1, (kt + 1 - klo) & 1);

        const uint32_t* bp = smw + (uint32_t)((kt - klo) & 1) * FBUFW;
        const float* amf = (const float*)(bp + F_AM);
        const int k0 = kt * BKT;

        float s[8][4];
#pragma unroll
        for (int nt = 0; nt < 8; nt++)
#pragma unroll
            for (int j = 0; j < 4; j++) s[nt][j] = 0.f;

#pragma unroll
        for (int kc = 0; kc < 4; kc++) {
#pragma unroll
            for (int nt = 0; nt < 8; nt++) {
                const uint32_t koff = (8 * nt + g) * 40 + 8 * kc + 2 * tg;
                uint2 kh = *(const uint2*)(bp + F_KHI + koff);
                uint2 kl = *(const uint2*)(bp + F_KLO + koff);
                MMA_BF16(s[nt], qfh[kc], kh.x, kh.y);
                MMA_BF16(s[nt], qfl[kc], kh.x, kh.y);
                MMA_BF16(s[nt], qfh[kc], kl.x, kl.y);
            }
        }

        const bool need_mask = (kt >= 2 * qt);
#pragma unroll
        for (int nt = 0; nt < 8; nt++) {
            const int kg = k0 + 8 * nt + 2 * tg;
            const float a0 = amf[8 * nt + 2 * tg];
            const float a1 = amf[8 * nt + 2 * tg + 1];
            if (need_mask) {
                s[nt][0] = (kg     <= qg0) ? s[nt][0] + a0 : MBIAS + a0;
                s[nt][1] = (kg + 1 <= qg0) ? s[nt][1] + a1 : MBIAS + a1;
                s[nt][2] = (kg     <= qg1) ? s[nt][2] + a0 : MBIAS + a0;
                s[nt][3] = (kg + 1 <= qg1) ? s[nt][3] + a1 : MBIAS + a1;
            } else {
                s[nt][0] += a0; s[nt][1] += a1;
                s[nt][2] += a0; s[nt][3] += a1;
            }
        }

        float t0 = -1e30f, t1 = -1e30f;
#pragma unroll
        for (int nt = 0; nt < 8; nt++) {
            t0 = fmaxf(t0, fmaxf(s[nt][0], s[nt][1]));
            t1 = fmaxf(t1, fmaxf(s[nt][2], s[nt][3]));
        }
#pragma unroll
        for (int off = 1; off <= 2; off <<= 1) {
            t0 = fmaxf(t0, __shfl_xor_sync(0xffffffffu, t0, off));
            t1 = fmaxf(t1, __shfl_xor_sync(0xffffffffu, t1, off));
        }
        const float mn0 = fmaxf(mx0, t0), mn1 = fmaxf(mx1, t1);
        const float corr0 = __expf(mx0 - mn0), corr1 = __expf(mx1 - mn1);
        mx0 = mn0; mx1 = mn1;

        float sum0 = 0.f, sum1 = 0.f;
#pragma unroll
        for (int nt = 0; nt < 8; nt++) {
            s[nt][0] = __expf(s[nt][0] - mn0);
            s[nt][1] = __expf(s[nt][1] - mn0);
            s[nt][2] = __expf(s[nt][2] - mn1);
            s[nt][3] = __expf(s[nt][3] - mn1);
            sum0 += s[nt][0] + s[nt][1];
            sum1 += s[nt][2] + s[nt][3];
        }
#pragma unroll
        for (int off = 1; off <= 2; off <<= 1) {
            sum0 += __shfl_xor_sync(0xffffffffu, sum0, off);
            sum1 += __shfl_xor_sync(0xffffffffu, sum1, off);
        }
        ls0 = ls0 * corr0 + sum0;
        ls1 = ls1 * corr1 + sum1;
#pragma unroll
        for (int nt = 0; nt < 8; nt++) {
            accO[nt][0] *= corr0; accO[nt][1] *= corr0;
            accO[nt][2] *= corr1; accO[nt][3] *= corr1;
        }

        uint32_t ph[4][4], pl[4][4];
#pragma unroll
        for (int kc = 0; kc < 4; kc++) {
            pack2(s[2 * kc][0],     s[2 * kc][1],     ph[kc][0], pl[kc][0]);
            pack2(s[2 * kc][2],     s[2 * kc][3],     ph[kc][1], pl[kc][1]);
            pack2(s[2 * kc + 1][0], s[2 * kc + 1][1], ph[kc][2], pl[kc][2]);
            pack2(s[2 * kc + 1][2], s[2 * kc + 1][3], ph[kc][3], pl[kc][3]);
        }

#pragma unroll
        for (int kc = 0; kc < 4; kc++) {
#pragma unroll
            for (int nt = 0; nt < 8; nt++) {
                const uint32_t voff = (kc * 4 + tg) * 136 + (8 * nt + g) * 2;
                uint2 vh = *(const uint2*)(bp + F_VHI + voff);
                uint2 vl = *(const uint2*)(bp + F_VLO + voff);
                MMA_BF16(accO[nt], ph[kc], vh.x, vh.y);
                MMA_BF16(accO[nt], pl[kc], vh.x, vh.y);
                MMA_BF16(accO[nt], ph[kc], vl.x, vl.y);
            }
        }
    }

    if (!split) {
        const float inv0 = 1.0f / ls0, inv1 = 1.0f / ls1;
        const int rt = b * 128 + qt * 8 + wid;
#pragma unroll
        for (int np = 0; np < 4; np++) {
            const int nt0 = 2 * np, nt1 = nt0 + 1;
            uint32_t w0h,w0l,w1h,w1l,w2h,w2l,w3h,w3l;
            pack2(accO[nt0][0] * inv0, accO[nt0][1] * inv0, w0h, w0l);
            pack2(accO[nt0][2] * inv1, accO[nt0][3] * inv1, w1h, w1l);
            pack2(accO[nt1][0] * inv0, accO[nt1][1] * inv0, w2h, w2l);
            pack2(accO[nt1][2] * inv1, accO[nt1][3] * inv1, w3h, w3l);
            const size_t fi = (((size_t)rt * 48 + h * 4 + np) * 32 + g * 4 + tg) * 4;
            *(uint4*)(g_ath2 + fi) = make_uint4(w0h, w1h, w2h, w3h);
            *(uint4*)(g_atl2 + fi) = make_uint4(w0l, w1l, w2l, w3l);
        }
    } else {
        const int item = (b * NH + h) * NSPLIT_QT + (qt - 8);
        const int sidx = item * 2 + sp;
        float* Op = g_oacc + (size_t)sidx * 128 * 64;
        const int r0 = qg0 - q0, r1 = r0 + 8;
#pragma unroll
        for (int nt = 0; nt < 8; nt++) {
            const int col = 8 * nt + 2 * tg;
            *(float2*)(Op + r0 * 64 + col) = make_float2(accO[nt][0], accO[nt][1]);
            *(float2*)(Op + r1 * 64 + col) = make_float2(accO[nt][2], accO[nt][3]);
        }
        if (tg == 0) {
            g_ml[(size_t)sidx * 256 + r0]       = mx0;
            g_ml[(size_t)sidx * 256 + 128 + r0] = ls0;
            g_ml[(size_t)sidx * 256 + r1]       = mx1;
            g_ml[(size_t)sidx * 256 + 128 + r1] = ls1;
        }
    }
}

// ---------------------------------------------------------------------------
// Merge the two kv-splits; writes frag-major A words.
// ---------------------------------------------------------------------------
__global__ __launch_bounds__(256)
void merge_split()
{
    const int item = blockIdx.y;
    const int qt = item % NSPLIT_QT + 8;
    const int hb = item / NSPLIT_QT;
    const int h = hb % NH, b = hb / NH;
    const int flat = blockIdx.x * 256 + threadIdx.x;
    const int r = flat >> 5, dp = flat & 31;

    const int s0 = item * 2, s1 = s0 + 1;
    const float m0 = g_ml[(size_t)s0 * 256 + r];
    const float l0 = g_ml[(size_t)s0 * 256 + 128 + r];
    const float m1 = g_ml[(size_t)s1 * 256 + r];
    const float l1 = g_ml[(size_t)s1 * 256 + 128 + r];
    const float m  = fmaxf(m0, m1);
    const float c0 = __expf(m0 - m), c1 = __expf(m1 - m);
    const float inv = 1.0f / (c0 * l0 + c1 * l1);

    const float2 o0 = *(const float2*)(g_oacc + ((size_t)s0 * 128 + r) * 64 + 2 * dp);
    const float2 o1 = *(const float2*)(g_oacc + ((size_t)s1 * 128 + r) * 64 + 2 * dp);
    const float v0 = (c0 * o0.x + c1 * o1.x) * inv;
    const float v1 = (c0 * o0.y + c1 * o1.y) * inv;
    uint32_t hh, ll;
    pack2(v0, v1, hh, ll);
    const int rowg = b * SEQ + qt * BQ + r;
    const int kw = h * 32 + dp;
    const size_t fi = (((size_t)(rowg >> 4) * 48 + (kw >> 3)) * 32 +
                       (rowg & 7) * 4 + (kw & 3)) * 4 +
                      ((rowg >> 3) & 1) + 2 * ((kw >> 2) & 1);
    g_ath2[fi] = hh;
    g_atl2[fi] = ll;
}

// ---------------------------------------------------------------------------
extern "C" void kernel_launch(void* const* d_in, const int* in_sizes, int n_in,
                              void* d_out, int out_size)
{
    const float* hidden = (const float*)d_in[0];
    const float* amask  = (const float*)d_in[1];
    const float* w_attn = (const float*)d_in[2];
    const float* b_attn = (const float*)d_in[3];
    const float* w_proj = (const float*)d_in[4];
    const float* b_proj = (const float*)d_in[5];
    float* out = (float*)d_out;

    cudaFuncSetAttribute(gemm_mma,
        cudaFuncAttributeMaxDynamicSharedMemorySize, GEMM_SMEM_BYTES);
    cudaFuncSetAttribute(flash_mma,
        cudaFuncAttributeMaxDynamicSharedMemorySize, FLASH_SMEM_BYTES);

    uint32_t *hh2, *hl2, *wah2, *wal2, *wph2, *wpl2, *ath2, *atl2;
    cudaGetSymbolAddress((void**)&hh2,  g_hh2);
    cudaGetSymbolAddress((void**)&hl2,  g_hl2);
    cudaGetSymbolAddress((void**)&wah2, g_wah2);
    cudaGetSymbolAddress((void**)&wal2, g_wal2);
    cudaGetSymbolAddress((void**)&wph2, g_wph2);
    cudaGetSymbolAddress((void**)&wpl2, g_wpl2);
    cudaGetSymbolAddress((void**)&ath2, g_ath2);
    cudaGetSymbolAddress((void**)&atl2, g_atl2);

    // 0) precompute operands: A frag-major, B frag-pair
    prep_row_frag<<<(MROWS / 16) * 48 / 8, 256>>>(hidden, hh2, hl2);
    prep_colpair_frag<<<48 * (3 * NX) * 4 / 256, 256>>>(w_attn, wah2, wal2, 3 * NX);
    prep_colpair_frag<<<48 * NX * 4 / 256, 256>>>(w_proj, wph2, wpl2, NX);

    // 1) QKV projection -> q (scaled) / k (pair-permuted) / v bf16 hi/lo
    gemm_mma<<<dim3(3 * NX / TN, MROWS / TM), 256, GEMM_SMEM_BYTES>>>(
        hh2, hl2, wah2, wal2, b_attn, nullptr, 3 * NX, 1);

    // 1b) V pair-row repack for uint2 flash fragments
    repack_v<<<PAIRS_H / 256, 256>>>();

    // 2) Causal flash attention, LPT split-KV (24 jobs per (h,b))
    flash_mma<<<dim3(24, NH, BSZ), 256, FLASH_SMEM_BYTES>>>(amask);

    // 2b) merge kv-splits
    merge_split<<<dim3(16, NITEMS), 256>>>();

    // 3) Output projection -> fp32 out
    gemm_mma<<<dim3(NX / TN, MROWS / TM), 256, GEMM_SMEM_BYTES>>>(
        ath2, atl2, wph2, wpl2, b_proj, out, NX, 2);
}